// round 8
// baseline (speedup 1.0000x reference)
#include <cuda_runtime.h>
#include <cuda_bf16.h>
#include <math.h>
#include <stdint.h>

#define Bn 2
#define Cn 64
#define CQn 8
#define Hn 270
#define Wn 480
#define HWn (Hn*Wn)
#define NPIX (Bn*HWn)
#define Hp 272   // padded H stride for transposed layouts

__device__ __forceinline__ uint32_t tf32c(float f){
    uint32_t r; asm("cvt.rna.tf32.f32 %0, %1;" : "=r"(r) : "f"(f)); return r;
}
__device__ __forceinline__ uint32_t bfpack(float lo, float hi){
    __nv_bfloat162 b = __floats2bfloat162_rn(lo, hi);
    return *(uint32_t*)&b;
}
__device__ __forceinline__ void mma_tf32(float* c, const uint32_t* a, const uint32_t* b){
    asm volatile("mma.sync.aligned.m16n8k8.row.col.f32.tf32.tf32.f32 "
        "{%0,%1,%2,%3}, {%4,%5,%6,%7}, {%8,%9}, {%0,%1,%2,%3};"
        : "+f"(c[0]),"+f"(c[1]),"+f"(c[2]),"+f"(c[3])
        : "r"(a[0]),"r"(a[1]),"r"(a[2]),"r"(a[3]), "r"(b[0]),"r"(b[1]));
}
__device__ __forceinline__ void mma_bf16(float* c, const uint32_t* a, const uint32_t* b){
    asm volatile("mma.sync.aligned.m16n8k16.row.col.f32.bf16.bf16.f32 "
        "{%0,%1,%2,%3}, {%4,%5,%6,%7}, {%8,%9}, {%0,%1,%2,%3};"
        : "+f"(c[0]),"+f"(c[1]),"+f"(c[2]),"+f"(c[3])
        : "r"(a[0]),"r"(a[1]),"r"(a[2]),"r"(a[3]), "r"(b[0]),"r"(b[1]));
}

// -------- scratch (device globals; allocation-free) --------
__device__ float g_q [Bn*CQn*HWn];        // [b][c8][h][w]
__device__ float g_k [Bn*CQn*HWn];
__device__ float g_v [Bn*Cn *HWn];        // [b][c][h][w]
__device__ float g_qT[Bn*Wn*CQn*Hp];      // [b][w][c8][h]
__device__ float g_kT[Bn*Wn*CQn*Hp];
__device__ float g_vT[Bn*Wn*Cn *Hp];      // [b][w][c][h]  (pad rows stay zero)
__device__ float g_ow [Bn*Cn*HWn];        // unnorm out_w
__device__ float g_ohT[Bn*Wn*Cn*Hp];      // unnorm out_h (transposed)
__device__ float g_sw [Bn*Hn*Wn];
__device__ float g_sh [Bn*Wn*Hn];
__device__ float g_inv[Bn*Hn*Wn];

// ================= K1: fused q/k/v projection via tf32 mma =================
// block = 128 thr (4 warps), 64 pixels. M=80 outputs (5 m16), N=64 px, K=64.
// warp w owns n-tiles {2w, 2w+1} (16 px), all 5 m-tiles.
__global__ __launch_bounds__(128) void proj_mma(
    const float* __restrict__ x,
    const float* __restrict__ Wq, const float* __restrict__ bq,
    const float* __restrict__ Wk, const float* __restrict__ bk,
    const float* __restrict__ Wv, const float* __restrict__ bv)
{
    __shared__ uint32_t ws[64*88];     // W transposed: [c][o], pitch 88
    __shared__ __align__(16) uint32_t xs[64*72];  // x tile tf32: [c][px], pitch 72
    __shared__ float bs[80];

    const int t = threadIdx.x;
    const int w = t >> 5, lane = t & 31, gp = lane >> 2, tid4 = lane & 3;

    for (int i = t; i < 80*64; i += 128) {
        int o = i >> 6, c = i & 63;
        float wv;
        if (o < 8)       wv = Wq[i];
        else if (o < 16) wv = Wk[i - 512];
        else             wv = Wv[i - 1024];
        ws[c*88 + o] = tf32c(wv);
    }
    if (t < 80) bs[t] = (t < 8) ? bq[t] : (t < 16 ? bk[t-8] : bv[t-16]);

    int p0 = blockIdx.x * 64;
    int b  = p0 / HWn;
    int r0 = p0 - b*HWn;
    const float* xb = x + (size_t)b*Cn*HWn + r0;
    // load 64x64 x tile, tf32 convert, vectorized
    for (int i = t; i < 64*16; i += 128) {
        int c = i >> 4, j4 = i & 15;
        float4 v = *(const float4*)&xb[(size_t)c*HWn + j4*4];
        uint4 u = make_uint4(tf32c(v.x), tf32c(v.y), tf32c(v.z), tf32c(v.w));
        *(uint4*)&xs[c*72 + j4*4] = u;
    }
    __syncthreads();

    float acc[5][2][4];
    #pragma unroll
    for (int jm = 0; jm < 5; jm++)
        #pragma unroll
        for (int jn = 0; jn < 2; jn++)
            acc[jm][jn][0]=acc[jm][jn][1]=acc[jm][jn][2]=acc[jm][jn][3]=0.f;

    #pragma unroll
    for (int kd = 0; kd < 8; kd++) {
        uint32_t bfr[2][2];
        #pragma unroll
        for (int jn = 0; jn < 2; jn++) {
            int n0 = (2*w + jn)*8;
            bfr[jn][0] = xs[(kd*8 + tid4    )*72 + n0 + gp];
            bfr[jn][1] = xs[(kd*8 + tid4 + 4)*72 + n0 + gp];
        }
        #pragma unroll
        for (int jm = 0; jm < 5; jm++) {
            uint32_t a[4];
            a[0] = ws[(kd*8 + tid4    )*88 + jm*16 + gp];
            a[1] = ws[(kd*8 + tid4    )*88 + jm*16 + gp + 8];
            a[2] = ws[(kd*8 + tid4 + 4)*88 + jm*16 + gp];
            a[3] = ws[(kd*8 + tid4 + 4)*88 + jm*16 + gp + 8];
            mma_tf32(acc[jm][0], a, bfr[0]);
            mma_tf32(acc[jm][1], a, bfr[1]);
        }
    }

    // store: rows o = jm*16+gp(+8), cols px = n0 + 2*tid4 (+1)
    #pragma unroll
    for (int jm = 0; jm < 5; jm++)
        #pragma unroll
        for (int jn = 0; jn < 2; jn++) {
            int n0 = (2*w + jn)*8;
            int px = r0 + n0 + 2*tid4;
            #pragma unroll
            for (int half = 0; half < 2; half++) {
                int o = jm*16 + gp + half*8;
                float bb = bs[o];
                float c0 = acc[jm][jn][2*half]   + bb;
                float c1 = acc[jm][jn][2*half+1] + bb;
                float* dst;
                if (o < 8)       dst = &g_q[(size_t)(b*CQn + o)*HWn + px];
                else if (o < 16) dst = &g_k[(size_t)(b*CQn + o-8)*HWn + px];
                else             dst = &g_v[(size_t)(b*Cn  + o-16)*HWn + px];
                dst[0] = c0; dst[1] = c1;
            }
        }
}

// ================= K2: combined tiled transpose (q,k,v in one launch) =================
// z = b*80 + ch: ch<8 -> q, ch<16 -> k, else v
__global__ __launch_bounds__(256) void transpose_all_kernel()
{
    __shared__ float tile[32][33];
    int z = blockIdx.z;
    int b = z / 80, ch = z - b*80;
    const float* in; float* out; int nch, c;
    if (ch < 8)       { in = g_q; out = g_qT; nch = CQn; c = ch; }
    else if (ch < 16) { in = g_k; out = g_kT; nch = CQn; c = ch - 8; }
    else              { in = g_v; out = g_vT; nch = Cn;  c = ch - 16; }

    int w0 = blockIdx.x * 32, h0 = blockIdx.y * 32;
    int tx = threadIdx.x & 31, ty = threadIdx.x >> 5;

    const float* plane = in + (size_t)(b*nch + c)*HWn;
    #pragma unroll
    for (int k2 = 0; k2 < 4; k2++) {
        int h = h0 + ty + 8*k2, w = w0 + tx;
        tile[ty+8*k2][tx] = (h < Hn) ? plane[h*Wn + w] : 0.f;
    }
    __syncthreads();
    #pragma unroll
    for (int k2 = 0; k2 < 4; k2++) {
        int w = w0 + ty + 8*k2, h = h0 + tx;
        if (h < Hn)
            out[((size_t)(b*Wn + w)*nch + c)*Hp + h] = tile[tx][ty+8*k2];
    }
}

// ================= K3: row attention via mma.sync =================
__global__ __launch_bounds__(128) void row_attn_mma(const float* __restrict__ dww)
{
    __shared__ uint32_t q_s[8*72];              // tf32 [c8][q]
    __shared__ uint32_t k_s[8*72];              // tf32 [c8][key]
    __shared__ __align__(8) __nv_bfloat16 v_s[64*72];  // [c][key]
    __shared__ float out_s[64*68];
    __shared__ float dwt[Wn];

    const int b = blockIdx.z, h = blockIdx.y, wbase = blockIdx.x*64;
    const int t = threadIdx.x;
    const int w = t >> 5, lane = t & 31, gp = lane >> 2, tid4 = lane & 3;
    const int r0 = wbase + 16*w + gp, r1 = r0 + 8;

    for (int i = t; i < Wn; i += 128) dwt[i] = dww[i];
    for (int i = t; i < 512; i += 128) {
        int c8 = i >> 6, ql = i & 63;
        int wq = wbase + ql;
        float v = (wq < Wn) ? g_q[(size_t)(b*CQn+c8)*HWn + h*Wn + wq] : 0.f;
        q_s[c8*72 + ql] = tf32c(v);
    }
    __syncthreads();

    uint32_t aq[4];
    aq[0] = q_s[tid4*72     + 16*w + gp];
    aq[1] = q_s[tid4*72     + 16*w + gp + 8];
    aq[2] = q_s[(tid4+4)*72 + 16*w + gp];
    aq[3] = q_s[(tid4+4)*72 + 16*w + gp + 8];

    float oc[8][4];
    #pragma unroll
    for (int j = 0; j < 8; j++) { oc[j][0]=oc[j][1]=oc[j][2]=oc[j][3]=0.f; }
    float s0 = 0.f, s1 = 0.f;

    for (int ch = 0; ch < 8; ch++) {
        const int k0 = ch*64;
        for (int i = t; i < 512; i += 128) {
            int c8 = i >> 6, kl = i & 63;
            int kg = k0 + kl;
            float v = (kg < Wn) ? g_k[(size_t)(b*CQn+c8)*HWn + h*Wn + kg] : 0.f;
            k_s[c8*72 + kl] = tf32c(v);
        }
        for (int i = t; i < 1024; i += 128) {
            int c = i >> 4, kq = i & 15;
            int kg = k0 + kq*4;
            float4 vv = make_float4(0.f,0.f,0.f,0.f);
            if (kg < Wn) vv = *(const float4*)&g_v[(size_t)(b*Cn+c)*HWn + h*Wn + kg];
            uint2 st = make_uint2(bfpack(vv.x, vv.y), bfpack(vv.z, vv.w));
            *(uint2*)&v_s[c*72 + kq*4] = st;
        }
        __syncthreads();

        float ec[8][4];
        #pragma unroll
        for (int j = 0; j < 8; j++) {
            ec[j][0]=ec[j][1]=ec[j][2]=ec[j][3]=0.f;
            uint32_t bk[2];
            bk[0] = k_s[tid4*72     + 8*j + gp];
            bk[1] = k_s[(tid4+4)*72 + 8*j + gp];
            mma_tf32(ec[j], aq, bk);
        }

        const uint32_t* v32 = (const uint32_t*)v_s;
        #pragma unroll
        for (int kd = 0; kd < 4; kd++) {
            int kgA = k0 + 16*kd + 2*tid4;
            int kgB = kgA + 8;
            float* eA = ec[2*kd];
            float* eB = ec[2*kd+1];
            int dA0 = abs(r0 - kgA);     if (dA0 > Wn-1) dA0 = Wn-1;
            int dA1 = abs(r0 - kgA - 1); if (dA1 > Wn-1) dA1 = Wn-1;
            int dA2 = abs(r1 - kgA);     if (dA2 > Wn-1) dA2 = Wn-1;
            int dA3 = abs(r1 - kgA - 1); if (dA3 > Wn-1) dA3 = Wn-1;
            int dB0 = abs(r0 - kgB);     if (dB0 > Wn-1) dB0 = Wn-1;
            int dB1 = abs(r0 - kgB - 1); if (dB1 > Wn-1) dB1 = Wn-1;
            int dB2 = abs(r1 - kgB);     if (dB2 > Wn-1) dB2 = Wn-1;
            int dB3 = abs(r1 - kgB - 1); if (dB3 > Wn-1) dB3 = Wn-1;
            float pA0 = (kgA   < Wn) ? __expf(eA[0]*dwt[dA0]) : 0.f;
            float pA1 = (kgA+1 < Wn) ? __expf(eA[1]*dwt[dA1]) : 0.f;
            float pA2 = (kgA   < Wn) ? __expf(eA[2]*dwt[dA2]) : 0.f;
            float pA3 = (kgA+1 < Wn) ? __expf(eA[3]*dwt[dA3]) : 0.f;
            float pB0 = (kgB   < Wn) ? __expf(eB[0]*dwt[dB0]) : 0.f;
            float pB1 = (kgB+1 < Wn) ? __expf(eB[1]*dwt[dB1]) : 0.f;
            float pB2 = (kgB   < Wn) ? __expf(eB[2]*dwt[dB2]) : 0.f;
            float pB3 = (kgB+1 < Wn) ? __expf(eB[3]*dwt[dB3]) : 0.f;
            s0 += pA0 + pA1 + pB0 + pB1;
            s1 += pA2 + pA3 + pB2 + pB3;

            uint32_t ap[4];
            ap[0] = bfpack(pA0, pA1);
            ap[1] = bfpack(pA2, pA3);
            ap[2] = bfpack(pB0, pB1);
            ap[3] = bfpack(pB2, pB3);

            #pragma unroll
            for (int jn = 0; jn < 8; jn++) {
                uint32_t bv[2];
                bv[0] = v32[(8*jn+gp)*36 + kd*8 + tid4];
                bv[1] = v32[(8*jn+gp)*36 + kd*8 + 4 + tid4];
                mma_bf16(oc[jn], ap, bv);
            }
        }
        __syncthreads();
    }

    s0 += __shfl_xor_sync(0xffffffffu, s0, 1);
    s0 += __shfl_xor_sync(0xffffffffu, s0, 2);
    s1 += __shfl_xor_sync(0xffffffffu, s1, 1);
    s1 += __shfl_xor_sync(0xffffffffu, s1, 2);
    if (tid4 == 0) {
        if (r0 < Wn) g_sw[(b*Hn + h)*Wn + r0] = s0;
        if (r1 < Wn) g_sw[(b*Hn + h)*Wn + r1] = s1;
    }

    #pragma unroll
    for (int jn = 0; jn < 8; jn++) {
        out_s[(8*jn+2*tid4  )*68 + 16*w + gp    ] = oc[jn][0];
        out_s[(8*jn+2*tid4+1)*68 + 16*w + gp    ] = oc[jn][1];
        out_s[(8*jn+2*tid4  )*68 + 16*w + gp + 8] = oc[jn][2];
        out_s[(8*jn+2*tid4+1)*68 + 16*w + gp + 8] = oc[jn][3];
    }
    __syncthreads();
    {
        int tq = t & 63, half = t >> 6;
        int wq = wbase + tq;
        if (wq < Wn) {
            #pragma unroll 4
            for (int i = 0; i < 32; i++) {
                int c = half*32 + i;
                g_ow[(size_t)(b*Cn + c)*HWn + h*Wn + wq] = out_s[c*68 + tq];
            }
        }
    }
}

// ================= K4: column attention via mma.sync (diag masked) =================
__global__ __launch_bounds__(128) void col_attn_mma(const float* __restrict__ dwh)
{
    __shared__ uint32_t q_s[8*72];
    __shared__ uint32_t k_s[8*72];
    __shared__ __align__(8) __nv_bfloat16 v_s[64*72];
    __shared__ float out_s[64*68];
    __shared__ float dwt[Hn];

    const int b = blockIdx.z, w = blockIdx.y, hbase = blockIdx.x*64;
    const int t = threadIdx.x;
    const int wp = t >> 5, lane = t & 31, gp = lane >> 2, tid4 = lane & 3;
    const int r0 = hbase + 16*wp + gp, r1 = r0 + 8;

    for (int i = t; i < Hn; i += 128) dwt[i] = dwh[i];
    for (int i = t; i < 512; i += 128) {
        int c8 = i >> 6, ql = i & 63;
        int hq = hbase + ql;
        float v = (hq < Hn) ? g_qT[((size_t)(b*Wn+w)*CQn + c8)*Hp + hq] : 0.f;
        q_s[c8*72 + ql] = tf32c(v);
    }
    __syncthreads();

    uint32_t aq[4];
    aq[0] = q_s[tid4*72     + 16*wp + gp];
    aq[1] = q_s[tid4*72     + 16*wp + gp + 8];
    aq[2] = q_s[(tid4+4)*72 + 16*wp + gp];
    aq[3] = q_s[(tid4+4)*72 + 16*wp + gp + 8];

    float oc[8][4];
    #pragma unroll
    for (int j = 0; j < 8; j++) { oc[j][0]=oc[j][1]=oc[j][2]=oc[j][3]=0.f; }
    float s0 = 0.f, s1 = 0.f;

    for (int ch = 0; ch < 5; ch++) {
        const int k0 = ch*64;
        for (int i = t; i < 512; i += 128) {
            int c8 = i >> 6, kl = i & 63;
            int kg = k0 + kl;
            float v = (kg < Hn) ? g_kT[((size_t)(b*Wn+w)*CQn + c8)*Hp + kg] : 0.f;
            k_s[c8*72 + kl] = tf32c(v);
        }
        for (int i = t; i < 1024; i += 128) {
            int c = i >> 4, kq = i & 15;
            int kg = k0 + kq*4;
            float4 vv = make_float4(0.f,0.f,0.f,0.f);
            if (kg < Hn)
                vv = *(const float4*)&g_vT[((size_t)(b*Wn+w)*Cn + c)*Hp + kg];
            uint2 st = make_uint2(bfpack(vv.x, vv.y), bfpack(vv.z, vv.w));
            *(uint2*)&v_s[c*72 + kq*4] = st;
        }
        __syncthreads();

        float ec[8][4];
        #pragma unroll
        for (int j = 0; j < 8; j++) {
            ec[j][0]=ec[j][1]=ec[j][2]=ec[j][3]=0.f;
            uint32_t bk[2];
            bk[0] = k_s[tid4*72     + 8*j + gp];
            bk[1] = k_s[(tid4+4)*72 + 8*j + gp];
            mma_tf32(ec[j], aq, bk);
        }

        const uint32_t* v32 = (const uint32_t*)v_s;
        #pragma unroll
        for (int kd = 0; kd < 4; kd++) {
            int kgA = k0 + 16*kd + 2*tid4;
            int kgB = kgA + 8;
            float* eA = ec[2*kd];
            float* eB = ec[2*kd+1];
            int dA0 = abs(r0 - kgA);     if (dA0 > Hn-1) dA0 = Hn-1;
            int dA1 = abs(r0 - kgA - 1); if (dA1 > Hn-1) dA1 = Hn-1;
            int dA2 = abs(r1 - kgA);     if (dA2 > Hn-1) dA2 = Hn-1;
            int dA3 = abs(r1 - kgA - 1); if (dA3 > Hn-1) dA3 = Hn-1;
            int dB0 = abs(r0 - kgB);     if (dB0 > Hn-1) dB0 = Hn-1;
            int dB1 = abs(r0 - kgB - 1); if (dB1 > Hn-1) dB1 = Hn-1;
            int dB2 = abs(r1 - kgB);     if (dB2 > Hn-1) dB2 = Hn-1;
            int dB3 = abs(r1 - kgB - 1); if (dB3 > Hn-1) dB3 = Hn-1;
            float pA0 = (kgA   < Hn && kgA   != r0) ? __expf(eA[0]*dwt[dA0]) : 0.f;
            float pA1 = (kgA+1 < Hn && kgA+1 != r0) ? __expf(eA[1]*dwt[dA1]) : 0.f;
            float pA2 = (kgA   < Hn && kgA   != r1) ? __expf(eA[2]*dwt[dA2]) : 0.f;
            float pA3 = (kgA+1 < Hn && kgA+1 != r1) ? __expf(eA[3]*dwt[dA3]) : 0.f;
            float pB0 = (kgB   < Hn && kgB   != r0) ? __expf(eB[0]*dwt[dB0]) : 0.f;
            float pB1 = (kgB+1 < Hn && kgB+1 != r0) ? __expf(eB[1]*dwt[dB1]) : 0.f;
            float pB2 = (kgB   < Hn && kgB   != r1) ? __expf(eB[2]*dwt[dB2]) : 0.f;
            float pB3 = (kgB+1 < Hn && kgB+1 != r1) ? __expf(eB[3]*dwt[dB3]) : 0.f;
            s0 += pA0 + pA1 + pB0 + pB1;
            s1 += pA2 + pA3 + pB2 + pB3;

            uint32_t ap[4];
            ap[0] = bfpack(pA0, pA1);
            ap[1] = bfpack(pA2, pA3);
            ap[2] = bfpack(pB0, pB1);
            ap[3] = bfpack(pB2, pB3);

            #pragma unroll
            for (int jn = 0; jn < 8; jn++) {
                uint32_t bv[2];
                bv[0] = v32[(8*jn+gp)*36 + kd*8 + tid4];
                bv[1] = v32[(8*jn+gp)*36 + kd*8 + 4 + tid4];
                mma_bf16(oc[jn], ap, bv);
            }
        }
        __syncthreads();
    }

    s0 += __shfl_xor_sync(0xffffffffu, s0, 1);
    s0 += __shfl_xor_sync(0xffffffffu, s0, 2);
    s1 += __shfl_xor_sync(0xffffffffu, s1, 1);
    s1 += __shfl_xor_sync(0xffffffffu, s1, 2);
    if (tid4 == 0) {
        if (r0 < Hn) g_sh[(b*Wn + w)*Hn + r0] = s0;
        if (r1 < Hn) g_sh[(b*Wn + w)*Hn + r1] = s1;
    }

    #pragma unroll
    for (int jn = 0; jn < 8; jn++) {
        out_s[(8*jn+2*tid4  )*68 + 16*wp + gp    ] = oc[jn][0];
        out_s[(8*jn+2*tid4+1)*68 + 16*wp + gp    ] = oc[jn][1];
        out_s[(8*jn+2*tid4  )*68 + 16*wp + gp + 8] = oc[jn][2];
        out_s[(8*jn+2*tid4+1)*68 + 16*wp + gp + 8] = oc[jn][3];
    }
    __syncthreads();
    {
        int tq = t & 63, half = t >> 6;
        int hq = hbase + tq;
        if (hq < Hn) {
            #pragma unroll 4
            for (int i = 0; i < 32; i++) {
                int c = half*32 + i;
                g_ohT[((size_t)(b*Wn+w)*Cn + c)*Hp + hq] = out_s[c*68 + tq];
            }
        }
    }
}

// ================= K4.5: per-pixel 1/(s_h+s_w) =================
__global__ __launch_bounds__(256) void stats_kernel()
{
    int i = blockIdx.x*256 + threadIdx.x;
    if (i >= NPIX) return;
    int b = i / HWn, r = i - b*HWn;
    int h = r / Wn, w = r - h*Wn;
    float s = g_sw[i] + g_sh[(b*Wn + w)*Hn + h];
    g_inv[i] = 1.0f / s;
}

// ================= K5: combine + residual =================
__global__ __launch_bounds__(256) void combine_kernel(
    const float* __restrict__ x, const float* __restrict__ gamma_p,
    float* __restrict__ out)
{
    __shared__ float tile[32][33];
    int bc = blockIdx.z;
    int b = bc >> 6, c = bc & 63;
    int w0 = blockIdx.x * 32, h0 = blockIdx.y * 32;
    int tx = threadIdx.x & 31, ty = threadIdx.x >> 5;

    #pragma unroll
    for (int k2 = 0; k2 < 4; k2++) {
        int w = w0 + ty + 8*k2, h = h0 + tx;
        float v = 0.f;
        if (h < Hn) v = g_ohT[((size_t)(b*Wn+w)*Cn + c)*Hp + h];
        tile[ty+8*k2][tx] = v;
    }
    __syncthreads();
    float gamma = gamma_p[0];
    #pragma unroll
    for (int k2 = 0; k2 < 4; k2++) {
        int h = h0 + ty + 8*k2, w = w0 + tx;
        if (h >= Hn) continue;
        float oh = tile[tx][ty+8*k2];
        size_t idx = (size_t)(b*Cn + c)*HWn + h*Wn + w;
        float ow = g_ow[idx];
        float iv = g_inv[(b*Hn + h)*Wn + w];
        out[idx] = gamma * (oh + ow) * iv + x[idx];
    }
}

// ================= launch =================
extern "C" void kernel_launch(void* const* d_in, const int* in_sizes, int n_in,
                              void* d_out, int out_size)
{
    const float* x     = (const float*)d_in[0];
    const float* Wq    = (const float*)d_in[1];
    const float* bq    = (const float*)d_in[2];
    const float* Wk    = (const float*)d_in[3];
    const float* bk    = (const float*)d_in[4];
    const float* Wv    = (const float*)d_in[5];
    const float* bv    = (const float*)d_in[6];
    const float* gamma = (const float*)d_in[7];
    const float* dwh   = (const float*)d_in[8];
    const float* dww   = (const float*)d_in[9];
    float* out = (float*)d_out;

    proj_mma<<<NPIX/64, 128>>>(x, Wq, bq, Wk, bk, Wv, bv);

    transpose_all_kernel<<<dim3(Wn/32, (Hn+31)/32, Bn*80), 256>>>();

    row_attn_mma<<<dim3(8, Hn, Bn), 128>>>(dww);
    col_attn_mma<<<dim3(5, Wn, Bn), 128>>>(dwh);

    stats_kernel<<<(NPIX + 255)/256, 256>>>();

    combine_kernel<<<dim3(Wn/32, (Hn+31)/32, Bn*Cn), 256>>>(x, gamma, out);
}

// round 13
// speedup vs baseline: 1.2632x; 1.2632x over previous
#include <cuda_runtime.h>
#include <cuda_bf16.h>
#include <stdint.h>

#define Bn 2
#define Cn 64
#define CQn 8
#define Hn 270
#define Wn 480
#define HWn (Hn*Wn)
#define NPIX (Bn*HWn)
#define Hp 272   // padded H stride for transposed layouts
#define ROWBLKS (8*Hn*Bn)   // 4320
#define COLBLKS (5*Wn*Bn)   // 4800

__device__ __forceinline__ uint32_t tf32c(float f){
    uint32_t r; asm("cvt.rna.tf32.f32 %0, %1;" : "=r"(r) : "f"(f)); return r;
}
__device__ __forceinline__ uint32_t bfpack(float lo, float hi){
    __nv_bfloat162 b = __floats2bfloat162_rn(lo, hi);
    return *(uint32_t*)&b;
}
__device__ __forceinline__ void mma_tf32(float* c, const uint32_t* a, const uint32_t* b){
    asm volatile("mma.sync.aligned.m16n8k8.row.col.f32.tf32.tf32.f32 "
        "{%0,%1,%2,%3}, {%4,%5,%6,%7}, {%8,%9}, {%0,%1,%2,%3};"
        : "+f"(c[0]),"+f"(c[1]),"+f"(c[2]),"+f"(c[3])
        : "r"(a[0]),"r"(a[1]),"r"(a[2]),"r"(a[3]), "r"(b[0]),"r"(b[1]));
}
__device__ __forceinline__ void mma_bf16(float* c, const uint32_t* a, const uint32_t* b){
    asm volatile("mma.sync.aligned.m16n8k16.row.col.f32.bf16.bf16.f32 "
        "{%0,%1,%2,%3}, {%4,%5,%6,%7}, {%8,%9}, {%0,%1,%2,%3};"
        : "+f"(c[0]),"+f"(c[1]),"+f"(c[2]),"+f"(c[3])
        : "r"(a[0]),"r"(a[1]),"r"(a[2]),"r"(a[3]), "r"(b[0]),"r"(b[1]));
}
__device__ __forceinline__ uint32_t s2u(const void* p){
    uint32_t a;
    asm("{ .reg .u64 t; cvta.to.shared.u64 t, %1; cvt.u32.u64 %0, t; }" : "=r"(a) : "l"(p));
    return a;
}
__device__ __forceinline__ void cp16(uint32_t saddr, const void* gptr){
    asm volatile("cp.async.cg.shared.global [%0], [%1], 16;" :: "r"(saddr), "l"(gptr) : "memory");
}
__device__ __forceinline__ void cp_commit(){ asm volatile("cp.async.commit_group;" ::: "memory"); }
__device__ __forceinline__ void cp_wait0(){ asm volatile("cp.async.wait_group 0;" ::: "memory"); }

// -------- scratch (device globals; allocation-free) --------
__device__ float g_q [Bn*CQn*HWn];            // [b][c8][h][w]
__device__ float g_k [Bn*CQn*HWn];
__device__ __nv_bfloat16 g_v [Bn*Cn*HWn];     // bf16 [b][c][h][w]
__device__ float g_qT[Bn*Wn*CQn*Hp];          // [b][w][c8][h]
__device__ float g_kT[Bn*Wn*CQn*Hp];
__device__ __nv_bfloat16 g_vT[Bn*Wn*Cn*Hp];   // bf16 [b][w][c][h] (pad rows zero)
__device__ float g_ow [Bn*Cn*HWn];            // unnorm out_w (f32)
__device__ float g_ohT[Bn*Wn*Cn*Hp];          // unnorm out_h (f32, transposed)
__device__ float g_sw [Bn*Hn*Wn];
__device__ float g_sh [Bn*Wn*Hn];
__device__ float g_inv[Bn*Hn*Wn];

// ================= K1: fused q/k/v projection via tf32 mma =================
__global__ __launch_bounds__(128) void proj_mma(
    const float* __restrict__ x,
    const float* __restrict__ Wq, const float* __restrict__ bq,
    const float* __restrict__ Wk, const float* __restrict__ bk,
    const float* __restrict__ Wv, const float* __restrict__ bv)
{
    __shared__ uint32_t ws[64*88];     // W transposed: [c][o], pitch 88
    __shared__ __align__(16) uint32_t xs[64*72];  // x tile tf32: [c][px], pitch 72
    __shared__ float bs[80];

    const int t = threadIdx.x;
    const int w = t >> 5, lane = t & 31, gp = lane >> 2, tid4 = lane & 3;

    for (int i = t; i < 80*64; i += 128) {
        int o = i >> 6, c = i & 63;
        float wv;
        if (o < 8)       wv = Wq[i];
        else if (o < 16) wv = Wk[i - 512];
        else             wv = Wv[i - 1024];
        ws[c*88 + o] = tf32c(wv);
    }
    if (t < 80) bs[t] = (t < 8) ? bq[t] : (t < 16 ? bk[t-8] : bv[t-16]);

    int p0 = blockIdx.x * 64;
    int b  = p0 / HWn;
    int r0 = p0 - b*HWn;
    const float* xb = x + (size_t)b*Cn*HWn + r0;
    for (int i = t; i < 64*16; i += 128) {
        int c = i >> 4, j4 = i & 15;
        float4 v = *(const float4*)&xb[(size_t)c*HWn + j4*4];
        uint4 u = make_uint4(tf32c(v.x), tf32c(v.y), tf32c(v.z), tf32c(v.w));
        *(uint4*)&xs[c*72 + j4*4] = u;
    }
    __syncthreads();

    float acc[5][2][4];
    #pragma unroll
    for (int jm = 0; jm < 5; jm++)
        #pragma unroll
        for (int jn = 0; jn < 2; jn++)
            acc[jm][jn][0]=acc[jm][jn][1]=acc[jm][jn][2]=acc[jm][jn][3]=0.f;

    #pragma unroll
    for (int kd = 0; kd < 8; kd++) {
        uint32_t bfr[2][2];
        #pragma unroll
        for (int jn = 0; jn < 2; jn++) {
            int n0 = (2*w + jn)*8;
            bfr[jn][0] = xs[(kd*8 + tid4    )*72 + n0 + gp];
            bfr[jn][1] = xs[(kd*8 + tid4 + 4)*72 + n0 + gp];
        }
        #pragma unroll
        for (int jm = 0; jm < 5; jm++) {
            uint32_t a[4];
            a[0] = ws[(kd*8 + tid4    )*88 + jm*16 + gp];
            a[1] = ws[(kd*8 + tid4    )*88 + jm*16 + gp + 8];
            a[2] = ws[(kd*8 + tid4 + 4)*88 + jm*16 + gp];
            a[3] = ws[(kd*8 + tid4 + 4)*88 + jm*16 + gp + 8];
            mma_tf32(acc[jm][0], a, bfr[0]);
            mma_tf32(acc[jm][1], a, bfr[1]);
        }
    }

    #pragma unroll
    for (int jm = 0; jm < 5; jm++)
        #pragma unroll
        for (int jn = 0; jn < 2; jn++) {
            int n0 = (2*w + jn)*8;
            int px = r0 + n0 + 2*tid4;
            #pragma unroll
            for (int half = 0; half < 2; half++) {
                int o = jm*16 + gp + half*8;
                float bb = bs[o];
                float c0 = acc[jm][jn][2*half]   + bb;
                float c1 = acc[jm][jn][2*half+1] + bb;
                if (o < 8) {
                    float* dst = &g_q[(size_t)(b*CQn + o)*HWn + px];
                    dst[0] = c0; dst[1] = c1;
                } else if (o < 16) {
                    float* dst = &g_k[(size_t)(b*CQn + o-8)*HWn + px];
                    dst[0] = c0; dst[1] = c1;
                } else {
                    *(uint32_t*)&g_v[(size_t)(b*Cn + o-16)*HWn + px] = bfpack(c0, c1);
                }
            }
        }
}

// ================= K2: combined transpose (q,k f32; v bf16) =================
__global__ __launch_bounds__(256) void transpose_all_kernel()
{
    __shared__ float tilef[32][33];
    __shared__ __nv_bfloat16 tileh[32][34];
    int z = blockIdx.z;
    int b = z / 80, ch = z - b*80;
    int w0 = blockIdx.x * 32, h0 = blockIdx.y * 32;
    int tx = threadIdx.x & 31, ty = threadIdx.x >> 5;

    if (ch < 16) {
        const float* in; float* out; int c;
        if (ch < 8) { in = g_q; out = g_qT; c = ch; }
        else        { in = g_k; out = g_kT; c = ch - 8; }
        const float* plane = in + (size_t)(b*CQn + c)*HWn;
        #pragma unroll
        for (int k2 = 0; k2 < 4; k2++) {
            int h = h0 + ty + 8*k2, w = w0 + tx;
            tilef[ty+8*k2][tx] = (h < Hn) ? plane[h*Wn + w] : 0.f;
        }
        __syncthreads();
        #pragma unroll
        for (int k2 = 0; k2 < 4; k2++) {
            int w = w0 + ty + 8*k2, h = h0 + tx;
            if (h < Hn)
                out[((size_t)(b*Wn + w)*CQn + c)*Hp + h] = tilef[tx][ty+8*k2];
        }
    } else {
        int c = ch - 16;
        const __nv_bfloat16* plane = g_v + (size_t)(b*Cn + c)*HWn;
        #pragma unroll
        for (int k2 = 0; k2 < 4; k2++) {
            int h = h0 + ty + 8*k2, w = w0 + tx;
            tileh[ty+8*k2][tx] = (h < Hn) ? plane[h*Wn + w] : __float2bfloat16(0.f);
        }
        __syncthreads();
        #pragma unroll
        for (int k2 = 0; k2 < 4; k2++) {
            int w = w0 + ty + 8*k2, h = h0 + tx;
            if (h < Hn)
                g_vT[((size_t)(b*Wn + w)*Cn + c)*Hp + h] = tileh[tx][ty+8*k2];
        }
    }
}

// ================= unified attention impl =================
template<bool COL>
__device__ __forceinline__ void attn_impl(
    const float* __restrict__ qb, const float* __restrict__ kb,
    const __nv_bfloat16* __restrict__ vb,
    float* __restrict__ ob, float* __restrict__ sb,
    long cs, int nkey, int nch, int tilebase, const float* __restrict__ dws,
    float* q_s, float* k0s, float* k1s,
    __nv_bfloat16* v0s, __nv_bfloat16* v1s,
    float* dwt, float* out_s)
{
    const int t = threadIdx.x;
    const int w5 = t >> 5, lane = t & 31, gp = lane >> 2, tid4 = lane & 3;
    const int r0 = tilebase + 16*w5 + gp, r1 = r0 + 8;

    for (int i = t; i < nkey; i += 128) dwt[i] = dws[i];

    const uint32_t q_u = s2u(q_s);
    uint32_t k_u[2] = { s2u(k0s), s2u(k1s) };
    uint32_t v_u[2] = { s2u(v0s), s2u(v1s) };
    float* k_sp[2] = { k0s, k1s };
    __nv_bfloat16* v_sp[2] = { v0s, v1s };

    // ---- stage Q ----
    if (!COL || tilebase + 64 <= nkey) {
        int row = t >> 4, seg = t & 15;
        cp16(q_u + (row*72 + seg*4)*4, qb + row*cs + tilebase + seg*4);
    } else {
        for (int i = t; i < 512; i += 128) {
            int c8 = i >> 6, ql = i & 63; int hq = tilebase + ql;
            q_s[c8*72 + ql] = (hq < nkey) ? qb[c8*cs + hq] : 0.f;
        }
    }

    // ---- staging helper ----
    auto stage = [&](int ch){
        int k0 = ch * 64; int buf = ch & 1;
        if (k0 + 64 <= nkey) {
            { int row = t >> 4, seg = t & 15;
              cp16(k_u[buf] + (row*72 + seg*4)*4, kb + row*cs + k0 + seg*4); }
            #pragma unroll
            for (int rr = 0; rr < 4; rr++) {
                int i = t + 128*rr; int row = i >> 3, seg = i & 7;
                cp16(v_u[buf] + (row*72 + seg*8)*2,
                     (const char*)vb + (row*cs + k0 + seg*8)*2);
            }
        } else {
            for (int i = t; i < 512; i += 128) {
                int c8 = i >> 6, kl = i & 63; int kg = k0 + kl;
                k_sp[buf][c8*72 + kl] = (kg < nkey) ? kb[c8*cs + kg] : 0.f;
            }
            for (int i = t; i < 2048; i += 128) {
                int row = i >> 5, p2 = i & 31; int kg = k0 + p2*2;
                uint32_t val = 0;
                if (kg < nkey) val = *(const uint32_t*)((const char*)vb + (row*cs + kg)*2);
                *(uint32_t*)((char*)v_sp[buf] + (row*72 + p2*2)*2) = val;
            }
        }
    };

    stage(0);
    cp_commit();
    cp_wait0();
    __syncthreads();

    const uint32_t* qu = (const uint32_t*)q_s;  // raw f32 bits read as tf32
    uint32_t aq[4];
    aq[0] = qu[tid4*72     + 16*w5 + gp];
    aq[1] = qu[tid4*72     + 16*w5 + gp + 8];
    aq[2] = qu[(tid4+4)*72 + 16*w5 + gp];
    aq[3] = qu[(tid4+4)*72 + 16*w5 + gp + 8];

    float oc[8][4];
    #pragma unroll
    for (int j = 0; j < 8; j++) { oc[j][0]=oc[j][1]=oc[j][2]=oc[j][3]=0.f; }
    float s0 = 0.f, s1 = 0.f;

    for (int ch = 0; ch < nch; ch++) {
        if (ch + 1 < nch) { stage(ch + 1); cp_commit(); }

        const int k0 = ch * 64;
        const int buf = ch & 1;
        const uint32_t* ku  = (const uint32_t*)k_sp[buf];
        const uint32_t* v32 = (const uint32_t*)v_sp[buf];

        float ec[8][4];
        #pragma unroll
        for (int j = 0; j < 8; j++) {
            ec[j][0]=ec[j][1]=ec[j][2]=ec[j][3]=0.f;
            uint32_t bk[2];
            bk[0] = ku[tid4*72     + 8*j + gp];
            bk[1] = ku[(tid4+4)*72 + 8*j + gp];
            mma_tf32(ec[j], aq, bk);
        }

        #pragma unroll
        for (int kd = 0; kd < 4; kd++) {
            int kgA = k0 + 16*kd + 2*tid4;
            int kgB = kgA + 8;
            float* eA = ec[2*kd];
            float* eB = ec[2*kd+1];
            // |d| <= nkey-1 always; no clamp needed for valid keys
            int dA0 = abs(r0 - kgA), dA1 = abs(r0 - kgA - 1);
            int dA2 = abs(r1 - kgA), dA3 = abs(r1 - kgA - 1);
            int dB0 = abs(r0 - kgB), dB1 = abs(r0 - kgB - 1);
            int dB2 = abs(r1 - kgB), dB3 = abs(r1 - kgB - 1);
            bool mA0, mA1, mA2, mA3, mB0, mB1, mB2, mB3;
            if (COL) {
                mA0 = (kgA   < nkey) && (kgA   != r0);
                mA1 = (kgA+1 < nkey) && (kgA+1 != r0);
                mA2 = (kgA   < nkey) && (kgA   != r1);
                mA3 = (kgA+1 < nkey) && (kgA+1 != r1);
                mB0 = (kgB   < nkey) && (kgB   != r0);
                mB1 = (kgB+1 < nkey) && (kgB+1 != r0);
                mB2 = (kgB   < nkey) && (kgB   != r1);
                mB3 = (kgB+1 < nkey) && (kgB+1 != r1);
            } else {
                mA0 = (kgA   < nkey); mA1 = (kgA+1 < nkey);
                mA2 = mA0;            mA3 = mA1;
                mB0 = (kgB   < nkey); mB1 = (kgB+1 < nkey);
                mB2 = mB0;            mB3 = mB1;
            }
            float pA0 = mA0 ? __expf(eA[0]*dwt[dA0]) : 0.f;
            float pA1 = mA1 ? __expf(eA[1]*dwt[dA1]) : 0.f;
            float pA2 = mA2 ? __expf(eA[2]*dwt[dA2]) : 0.f;
            float pA3 = mA3 ? __expf(eA[3]*dwt[dA3]) : 0.f;
            float pB0 = mB0 ? __expf(eB[0]*dwt[dB0]) : 0.f;
            float pB1 = mB1 ? __expf(eB[1]*dwt[dB1]) : 0.f;
            float pB2 = mB2 ? __expf(eB[2]*dwt[dB2]) : 0.f;
            float pB3 = mB3 ? __expf(eB[3]*dwt[dB3]) : 0.f;
            s0 += pA0 + pA1 + pB0 + pB1;
            s1 += pA2 + pA3 + pB2 + pB3;

            uint32_t ap[4];
            ap[0] = bfpack(pA0, pA1);
            ap[1] = bfpack(pA2, pA3);
            ap[2] = bfpack(pB0, pB1);
            ap[3] = bfpack(pB2, pB3);

            #pragma unroll
            for (int jn = 0; jn < 8; jn++) {
                uint32_t bv[2];
                bv[0] = v32[(8*jn+gp)*36 + kd*8 + tid4];
                bv[1] = v32[(8*jn+gp)*36 + kd*8 + 4 + tid4];
                mma_bf16(oc[jn], ap, bv);
            }
        }

        cp_wait0();
        __syncthreads();
    }

    s0 += __shfl_xor_sync(0xffffffffu, s0, 1);
    s0 += __shfl_xor_sync(0xffffffffu, s0, 2);
    s1 += __shfl_xor_sync(0xffffffffu, s1, 1);
    s1 += __shfl_xor_sync(0xffffffffu, s1, 2);
    if (tid4 == 0) {
        if (r0 < nkey) sb[r0] = s0;
        if (r1 < nkey) sb[r1] = s1;
    }

    #pragma unroll
    for (int jn = 0; jn < 8; jn++) {
        out_s[(8*jn+2*tid4  )*68 + 16*w5 + gp    ] = oc[jn][0];
        out_s[(8*jn+2*tid4+1)*68 + 16*w5 + gp    ] = oc[jn][1];
        out_s[(8*jn+2*tid4  )*68 + 16*w5 + gp + 8] = oc[jn][2];
        out_s[(8*jn+2*tid4+1)*68 + 16*w5 + gp + 8] = oc[jn][3];
    }
    __syncthreads();
    {
        int tq = t & 63, half = t >> 6;
        int q = tilebase + tq;
        if (q < nkey) {
            #pragma unroll 4
            for (int i = 0; i < 32; i++) {
                int c = half*32 + i;
                ob[(size_t)c*cs + q] = out_s[c*68 + tq];
            }
        }
    }
}

// ================= K3: merged row+col attention =================
__global__ __launch_bounds__(128) void attn_kernel(
    const float* __restrict__ dwh, const float* __restrict__ dww)
{
    __shared__ float q_s[8*72];
    __shared__ float k_s[2][8*72];
    __shared__ __align__(16) __nv_bfloat16 v_s[2][64*72];
    __shared__ float dwt[Wn];
    __shared__ float out_s[64*68];

    int id = blockIdx.x;
    if (id < ROWBLKS) {
        int b = id / (8*Hn); int r = id % (8*Hn); int h = r >> 3; int wt = r & 7;
        attn_impl<false>(
            g_q + (size_t)b*CQn*HWn + h*Wn,
            g_k + (size_t)b*CQn*HWn + h*Wn,
            g_v + (size_t)b*Cn*HWn + h*Wn,
            g_ow + (size_t)b*Cn*HWn + h*Wn,
            g_sw + (size_t)(b*Hn + h)*Wn,
            (long)HWn, Wn, 8, wt*64, dww,
            q_s, k_s[0], k_s[1], v_s[0], v_s[1], dwt, out_s);
    } else {
        int j = id - ROWBLKS;
        int b = j / (5*Wn); int r = j % (5*Wn); int w = r / 5; int ht = r % 5;
        attn_impl<true>(
            g_qT + (size_t)(b*Wn + w)*CQn*Hp,
            g_kT + (size_t)(b*Wn + w)*CQn*Hp,
            g_vT + (size_t)(b*Wn + w)*Cn*Hp,
            g_ohT + (size_t)(b*Wn + w)*Cn*Hp,
            g_sh + (size_t)(b*Wn + w)*Hn,
            (long)Hp, Hn, 5, ht*64, dwh,
            q_s, k_s[0], k_s[1], v_s[0], v_s[1], dwt, out_s);
    }
}

// ================= K4: per-pixel 1/(s_h+s_w) =================
__global__ __launch_bounds__(256) void stats_kernel()
{
    int i = blockIdx.x*256 + threadIdx.x;
    if (i >= NPIX) return;
    int b = i / HWn, r = i - b*HWn;
    int h = r / Wn, w = r - h*Wn;
    float s = g_sw[i] + g_sh[(b*Wn + w)*Hn + h];
    g_inv[i] = 1.0f / s;
}

// ================= K5: combine + residual =================
__global__ __launch_bounds__(256) void combine_kernel(
    const float* __restrict__ x, const float* __restrict__ gamma_p,
    float* __restrict__ out)
{
    __shared__ float tile[32][33];
    int bc = blockIdx.z;
    int b = bc >> 6, c = bc & 63;
    int w0 = blockIdx.x * 32, h0 = blockIdx.y * 32;
    int tx = threadIdx.x & 31, ty = threadIdx.x >> 5;

    #pragma unroll
    for (int k2 = 0; k2 < 4; k2++) {
        int w = w0 + ty + 8*k2, h = h0 + tx;
        float v = 0.f;
        if (h < Hn) v = g_ohT[((size_t)(b*Wn+w)*Cn + c)*Hp + h];
        tile[ty+8*k2][tx] = v;
    }
    __syncthreads();
    float gamma = gamma_p[0];
    #pragma unroll
    for (int k2 = 0; k2 < 4; k2++) {
        int h = h0 + ty + 8*k2, w = w0 + tx;
        if (h >= Hn) continue;
        float oh = tile[tx][ty+8*k2];
        size_t idx = (size_t)(b*Cn + c)*HWn + h*Wn + w;
        float ow = g_ow[idx];
        float iv = g_inv[(b*Hn + h)*Wn + w];
        out[idx] = gamma * (oh + ow) * iv + x[idx];
    }
}

// ================= launch =================
extern "C" void kernel_launch(void* const* d_in, const int* in_sizes, int n_in,
                              void* d_out, int out_size)
{
    const float* x     = (const float*)d_in[0];
    const float* Wq    = (const float*)d_in[1];
    const float* bq    = (const float*)d_in[2];
    const float* Wk    = (const float*)d_in[3];
    const float* bk    = (const float*)d_in[4];
    const float* Wv    = (const float*)d_in[5];
    const float* bv    = (const float*)d_in[6];
    const float* gamma = (const float*)d_in[7];
    const float* dwh   = (const float*)d_in[8];
    const float* dww   = (const float*)d_in[9];
    float* out = (float*)d_out;

    proj_mma<<<NPIX/64, 128>>>(x, Wq, bq, Wk, bk, Wv, bv);

    transpose_all_kernel<<<dim3(Wn/32, (Hn+31)/32, Bn*80), 256>>>();

    attn_kernel<<<ROWBLKS + COLBLKS, 128>>>(dwh, dww);

    stats_kernel<<<(NPIX + 255)/256, 256>>>();

    combine_kernel<<<dim3(Wn/32, (Hn+31)/32, Bn*Cn), 256>>>(x, gamma, out);
}

// round 17
// speedup vs baseline: 1.5010x; 1.1883x over previous
#include <cuda_runtime.h>
#include <cuda_bf16.h>
#include <cuda_fp16.h>
#include <stdint.h>

#define Bn 2
#define Cn 64
#define CQn 8
#define Hn 270
#define Wn 480
#define HWn (Hn*Wn)
#define NPIX (Bn*HWn)
#define Hp 272   // padded H stride for transposed layouts
#define ROWBLKS (8*Hn*Bn)   // 4320
#define COLBLKS (5*Wn*Bn)   // 4800

template<bool B> struct BC { static constexpr bool value = B; };

__device__ __forceinline__ uint32_t tf32c(float f){
    uint32_t r; asm("cvt.rna.tf32.f32 %0, %1;" : "=r"(r) : "f"(f)); return r;
}
__device__ __forceinline__ uint32_t bfpack(float lo, float hi){
    __nv_bfloat162 b = __floats2bfloat162_rn(lo, hi);
    return *(uint32_t*)&b;
}
__device__ __forceinline__ void mma_tf32(float* c, const uint32_t* a, const uint32_t* b){
    asm volatile("mma.sync.aligned.m16n8k8.row.col.f32.tf32.tf32.f32 "
        "{%0,%1,%2,%3}, {%4,%5,%6,%7}, {%8,%9}, {%0,%1,%2,%3};"
        : "+f"(c[0]),"+f"(c[1]),"+f"(c[2]),"+f"(c[3])
        : "r"(a[0]),"r"(a[1]),"r"(a[2]),"r"(a[3]), "r"(b[0]),"r"(b[1]));
}
__device__ __forceinline__ void mma_bf16(float* c, const uint32_t* a, const uint32_t* b){
    asm volatile("mma.sync.aligned.m16n8k16.row.col.f32.bf16.bf16.f32 "
        "{%0,%1,%2,%3}, {%4,%5,%6,%7}, {%8,%9}, {%0,%1,%2,%3};"
        : "+f"(c[0]),"+f"(c[1]),"+f"(c[2]),"+f"(c[3])
        : "r"(a[0]),"r"(a[1]),"r"(a[2]),"r"(a[3]), "r"(b[0]),"r"(b[1]));
}
__device__ __forceinline__ uint32_t s2u(const void* p){
    uint32_t a;
    asm("{ .reg .u64 t; cvta.to.shared.u64 t, %1; cvt.u32.u64 %0, t; }" : "=r"(a) : "l"(p));
    return a;
}
__device__ __forceinline__ void cp16(uint32_t saddr, const void* gptr){
    asm volatile("cp.async.cg.shared.global [%0], [%1], 16;" :: "r"(saddr), "l"(gptr) : "memory");
}
__device__ __forceinline__ void cp_commit(){ asm volatile("cp.async.commit_group;" ::: "memory"); }
__device__ __forceinline__ void cp_wait0(){ asm volatile("cp.async.wait_group 0;" ::: "memory"); }

// -------- scratch (device globals; allocation-free) --------
__device__ float g_q [Bn*CQn*HWn];            // [b][c8][h][w]
__device__ float g_k [Bn*CQn*HWn];
__device__ __nv_bfloat16 g_v [Bn*Cn*HWn];     // bf16 [b][c][h][w]
__device__ float g_qT[Bn*Wn*CQn*Hp];          // [b][w][c8][h]
__device__ float g_kT[Bn*Wn*CQn*Hp];
__device__ __nv_bfloat16 g_vT[Bn*Wn*Cn*Hp];   // bf16 [b][w][c][h] (pad rows zero)
__device__ __half g_ow [Bn*Cn*HWn];           // unnorm out_w (fp16)
__device__ __half g_ohT[Bn*Wn*Cn*Hp];         // unnorm out_h (fp16, transposed)
__device__ float g_sw [Bn*Hn*Wn];
__device__ float g_sh [Bn*Wn*Hn];
__device__ float g_inv[Bn*Hn*Wn];

// ================= K1: fused q/k/v projection via tf32 mma =================
__global__ __launch_bounds__(128) void proj_mma(
    const float* __restrict__ x,
    const float* __restrict__ Wq, const float* __restrict__ bq,
    const float* __restrict__ Wk, const float* __restrict__ bk,
    const float* __restrict__ Wv, const float* __restrict__ bv)
{
    __shared__ uint32_t ws[64*88];     // W transposed: [c][o], pitch 88
    __shared__ __align__(16) uint32_t xs[64*72];  // x tile tf32: [c][px], pitch 72
    __shared__ float bs[80];

    const int t = threadIdx.x;
    const int w = t >> 5, lane = t & 31, gp = lane >> 2, tid4 = lane & 3;

    for (int i = t; i < 80*64; i += 128) {
        int o = i >> 6, c = i & 63;
        float wv;
        if (o < 8)       wv = Wq[i];
        else if (o < 16) wv = Wk[i - 512];
        else             wv = Wv[i - 1024];
        ws[c*88 + o] = tf32c(wv);
    }
    if (t < 80) bs[t] = (t < 8) ? bq[t] : (t < 16 ? bk[t-8] : bv[t-16]);

    int p0 = blockIdx.x * 64;
    int b  = p0 / HWn;
    int r0 = p0 - b*HWn;
    const float* xb = x + (size_t)b*Cn*HWn + r0;
    for (int i = t; i < 64*16; i += 128) {
        int c = i >> 4, j4 = i & 15;
        float4 v = *(const float4*)&xb[(size_t)c*HWn + j4*4];
        uint4 u = make_uint4(tf32c(v.x), tf32c(v.y), tf32c(v.z), tf32c(v.w));
        *(uint4*)&xs[c*72 + j4*4] = u;
    }
    __syncthreads();

    float acc[5][2][4];
    #pragma unroll
    for (int jm = 0; jm < 5; jm++)
        #pragma unroll
        for (int jn = 0; jn < 2; jn++)
            acc[jm][jn][0]=acc[jm][jn][1]=acc[jm][jn][2]=acc[jm][jn][3]=0.f;

    #pragma unroll
    for (int kd = 0; kd < 8; kd++) {
        uint32_t bfr[2][2];
        #pragma unroll
        for (int jn = 0; jn < 2; jn++) {
            int n0 = (2*w + jn)*8;
            bfr[jn][0] = xs[(kd*8 + tid4    )*72 + n0 + gp];
            bfr[jn][1] = xs[(kd*8 + tid4 + 4)*72 + n0 + gp];
        }
        #pragma unroll
        for (int jm = 0; jm < 5; jm++) {
            uint32_t a[4];
            a[0] = ws[(kd*8 + tid4    )*88 + jm*16 + gp];
            a[1] = ws[(kd*8 + tid4    )*88 + jm*16 + gp + 8];
            a[2] = ws[(kd*8 + tid4 + 4)*88 + jm*16 + gp];
            a[3] = ws[(kd*8 + tid4 + 4)*88 + jm*16 + gp + 8];
            mma_tf32(acc[jm][0], a, bfr[0]);
            mma_tf32(acc[jm][1], a, bfr[1]);
        }
    }

    #pragma unroll
    for (int jm = 0; jm < 5; jm++)
        #pragma unroll
        for (int jn = 0; jn < 2; jn++) {
            int n0 = (2*w + jn)*8;
            int px = r0 + n0 + 2*tid4;
            #pragma unroll
            for (int half = 0; half < 2; half++) {
                int o = jm*16 + gp + half*8;
                float bb = bs[o];
                float c0 = acc[jm][jn][2*half]   + bb;
                float c1 = acc[jm][jn][2*half+1] + bb;
                if (o < 8) {
                    float* dst = &g_q[(size_t)(b*CQn + o)*HWn + px];
                    dst[0] = c0; dst[1] = c1;
                } else if (o < 16) {
                    float* dst = &g_k[(size_t)(b*CQn + o-8)*HWn + px];
                    dst[0] = c0; dst[1] = c1;
                } else {
                    *(uint32_t*)&g_v[(size_t)(b*Cn + o-16)*HWn + px] = bfpack(c0, c1);
                }
            }
        }
}

// ================= K2: combined transpose (q,k f32; v bf16) =================
__global__ __launch_bounds__(256) void transpose_all_kernel()
{
    __shared__ float tilef[32][33];
    __shared__ __nv_bfloat16 tileh[32][34];
    int z = blockIdx.z;
    int b = z / 80, ch = z - b*80;
    int w0 = blockIdx.x * 32, h0 = blockIdx.y * 32;
    int tx = threadIdx.x & 31, ty = threadIdx.x >> 5;

    if (ch < 16) {
        const float* in; float* out; int c;
        if (ch < 8) { in = g_q; out = g_qT; c = ch; }
        else        { in = g_k; out = g_kT; c = ch - 8; }
        const float* plane = in + (size_t)(b*CQn + c)*HWn;
        #pragma unroll
        for (int k2 = 0; k2 < 4; k2++) {
            int h = h0 + ty + 8*k2, w = w0 + tx;
            tilef[ty+8*k2][tx] = (h < Hn) ? plane[h*Wn + w] : 0.f;
        }
        __syncthreads();
        #pragma unroll
        for (int k2 = 0; k2 < 4; k2++) {
            int w = w0 + ty + 8*k2, h = h0 + tx;
            if (h < Hn)
                out[((size_t)(b*Wn + w)*CQn + c)*Hp + h] = tilef[tx][ty+8*k2];
        }
    } else {
        int c = ch - 16;
        const __nv_bfloat16* plane = g_v + (size_t)(b*Cn + c)*HWn;
        #pragma unroll
        for (int k2 = 0; k2 < 4; k2++) {
            int h = h0 + ty + 8*k2, w = w0 + tx;
            tileh[ty+8*k2][tx] = (h < Hn) ? plane[h*Wn + w] : __float2bfloat16(0.f);
        }
        __syncthreads();
        #pragma unroll
        for (int k2 = 0; k2 < 4; k2++) {
            int w = w0 + ty + 8*k2, h = h0 + tx;
            if (h < Hn)
                g_vT[((size_t)(b*Wn + w)*Cn + c)*Hp + h] = tileh[tx][ty+8*k2];
        }
    }
}

// ================= unified attention impl =================
template<bool COL>
__device__ __forceinline__ void attn_impl(
    const float* __restrict__ qb, const float* __restrict__ kb,
    const __nv_bfloat16* __restrict__ vb,
    __half* __restrict__ ob, float* __restrict__ sb,
    long cs, int nkey, int nch, int tilebase, const float* __restrict__ dws,
    float* q_s, float* k0s, float* k1s,
    __nv_bfloat16* v0s, __nv_bfloat16* v1s,
    float* dwt, float* out_s)
{
    const int t = threadIdx.x;
    const int w5 = t >> 5, lane = t & 31, gp = lane >> 2, tid4 = lane & 3;
    const int r0 = tilebase + 16*w5 + gp, r1 = r0 + 8;

    for (int i = t; i < nkey; i += 128) dwt[i] = dws[i];

    const uint32_t q_u = s2u(q_s);
    uint32_t k_u[2] = { s2u(k0s), s2u(k1s) };
    uint32_t v_u[2] = { s2u(v0s), s2u(v1s) };
    float* k_sp[2] = { k0s, k1s };
    __nv_bfloat16* v_sp[2] = { v0s, v1s };

    // ---- stage Q (fast path ONLY when the whole 64-wide tile is in-bounds;
    //      tail tiles (row wt=7, col ht=4) must take the guarded path to avoid
    //      cp.async reads past the end of the q plane/array) ----
    if (tilebase + 64 <= nkey) {
        int row = t >> 4, seg = t & 15;
        cp16(q_u + (row*72 + seg*4)*4, qb + row*cs + tilebase + seg*4);
    } else {
        for (int i = t; i < 512; i += 128) {
            int c8 = i >> 6, ql = i & 63; int hq = tilebase + ql;
            q_s[c8*72 + ql] = (hq < nkey) ? qb[c8*cs + hq] : 0.f;
        }
    }

    // ---- staging helper ----
    auto stage = [&](int ch){
        int k0 = ch * 64; int buf = ch & 1;
        if (k0 + 64 <= nkey) {
            { int row = t >> 4, seg = t & 15;
              cp16(k_u[buf] + (row*72 + seg*4)*4, kb + row*cs + k0 + seg*4); }
            #pragma unroll
            for (int rr = 0; rr < 4; rr++) {
                int i = t + 128*rr; int row = i >> 3, seg = i & 7;
                cp16(v_u[buf] + (row*72 + seg*8)*2,
                     (const char*)vb + (row*cs + k0 + seg*8)*2);
            }
        } else {
            for (int i = t; i < 512; i += 128) {
                int c8 = i >> 6, kl = i & 63; int kg = k0 + kl;
                k_sp[buf][c8*72 + kl] = (kg < nkey) ? kb[c8*cs + kg] : 0.f;
            }
            for (int i = t; i < 2048; i += 128) {
                int row = i >> 5, p2 = i & 31; int kg = k0 + p2*2;
                uint32_t val = 0;
                if (kg < nkey) val = *(const uint32_t*)((const char*)vb + (row*cs + kg)*2);
                *(uint32_t*)((char*)v_sp[buf] + (row*72 + p2*2)*2) = val;
            }
        }
    };

    stage(0);
    cp_commit();
    cp_wait0();
    __syncthreads();

    const uint32_t* qu = (const uint32_t*)q_s;  // raw f32 bits read as tf32
    uint32_t aq[4];
    aq[0] = qu[tid4*72     + 16*w5 + gp];
    aq[1] = qu[tid4*72     + 16*w5 + gp + 8];
    aq[2] = qu[(tid4+4)*72 + 16*w5 + gp];
    aq[3] = qu[(tid4+4)*72 + 16*w5 + gp + 8];

    float oc[8][4];
    #pragma unroll
    for (int j = 0; j < 8; j++) { oc[j][0]=oc[j][1]=oc[j][2]=oc[j][3]=0.f; }
    float s0 = 0.f, s1 = 0.f;

    for (int ch = 0; ch < nch; ch++) {
        if (ch + 1 < nch) { stage(ch + 1); cp_commit(); }

        const int k0 = ch * 64;
        const int buf = ch & 1;
        const uint32_t* ku  = (const uint32_t*)k_sp[buf];
        const uint32_t* v32 = (const uint32_t*)v_sp[buf];

        // specialized chunk body: MASKED = bounds checks, DIAG = diagonal mask
        auto body = [&](auto mc, auto dc){
            constexpr bool MASKED = decltype(mc)::value;
            constexpr bool DIAG   = decltype(dc)::value;
            #pragma unroll
            for (int kd = 0; kd < 4; kd++) {
                float eA[4] = {0.f,0.f,0.f,0.f}, eB[4] = {0.f,0.f,0.f,0.f};
                uint32_t bkA[2], bkB[2];
                bkA[0] = ku[tid4*72     + 8*(2*kd  ) + gp];
                bkA[1] = ku[(tid4+4)*72 + 8*(2*kd  ) + gp];
                bkB[0] = ku[tid4*72     + 8*(2*kd+1) + gp];
                bkB[1] = ku[(tid4+4)*72 + 8*(2*kd+1) + gp];
                mma_tf32(eA, aq, bkA);
                mma_tf32(eB, aq, bkB);

                int kgA = k0 + 16*kd + 2*tid4;
                int kgB = kgA + 8;
                int dA0 = abs(r0 - kgA), dA1 = abs(r0 - kgA - 1);
                int dA2 = abs(r1 - kgA), dA3 = abs(r1 - kgA - 1);
                int dB0 = abs(r0 - kgB), dB1 = abs(r0 - kgB - 1);
                int dB2 = abs(r1 - kgB), dB3 = abs(r1 - kgB - 1);
                // clamp (tail query tiles have r beyond nkey; keep dwt reads in-bounds)
                if (dA0 > nkey-1) dA0 = nkey-1;
                if (dA1 > nkey-1) dA1 = nkey-1;
                if (dA2 > nkey-1) dA2 = nkey-1;
                if (dA3 > nkey-1) dA3 = nkey-1;
                if (dB0 > nkey-1) dB0 = nkey-1;
                if (dB1 > nkey-1) dB1 = nkey-1;
                if (dB2 > nkey-1) dB2 = nkey-1;
                if (dB3 > nkey-1) dB3 = nkey-1;

                float pA0 = __expf(eA[0]*dwt[dA0]);
                float pA1 = __expf(eA[1]*dwt[dA1]);
                float pA2 = __expf(eA[2]*dwt[dA2]);
                float pA3 = __expf(eA[3]*dwt[dA3]);
                float pB0 = __expf(eB[0]*dwt[dB0]);
                float pB1 = __expf(eB[1]*dwt[dB1]);
                float pB2 = __expf(eB[2]*dwt[dB2]);
                float pB3 = __expf(eB[3]*dwt[dB3]);
                if (MASKED) {
                    if (kgA   >= nkey) { pA0 = 0.f; pA2 = 0.f; }
                    if (kgA+1 >= nkey) { pA1 = 0.f; pA3 = 0.f; }
                    if (kgB   >= nkey) { pB0 = 0.f; pB2 = 0.f; }
                    if (kgB+1 >= nkey) { pB1 = 0.f; pB3 = 0.f; }
                }
                if (DIAG) {
                    if (kgA   == r0) pA0 = 0.f;
                    if (kgA+1 == r0) pA1 = 0.f;
                    if (kgA   == r1) pA2 = 0.f;
                    if (kgA+1 == r1) pA3 = 0.f;
                    if (kgB   == r0) pB0 = 0.f;
                    if (kgB+1 == r0) pB1 = 0.f;
                    if (kgB   == r1) pB2 = 0.f;
                    if (kgB+1 == r1) pB3 = 0.f;
                }
                s0 += pA0 + pA1 + pB0 + pB1;
                s1 += pA2 + pA3 + pB2 + pB3;

                uint32_t ap[4];
                ap[0] = bfpack(pA0, pA1);
                ap[1] = bfpack(pA2, pA3);
                ap[2] = bfpack(pB0, pB1);
                ap[3] = bfpack(pB2, pB3);

                #pragma unroll
                for (int jn = 0; jn < 8; jn++) {
                    uint32_t bv[2];
                    bv[0] = v32[(8*jn+gp)*36 + kd*8 + tid4];
                    bv[1] = v32[(8*jn+gp)*36 + kd*8 + 4 + tid4];
                    mma_bf16(oc[jn], ap, bv);
                }
            }
        };

        bool full = (k0 + 64 <= nkey);
        bool diag = COL && (k0 == tilebase);
        if (full) {
            if (diag) body(BC<false>{}, BC<true >{});
            else      body(BC<false>{}, BC<false>{});
        } else {
            if (diag) body(BC<true >{}, BC<true >{});
            else      body(BC<true >{}, BC<false>{});
        }

        cp_wait0();
        __syncthreads();
    }

    s0 += __shfl_xor_sync(0xffffffffu, s0, 1);
    s0 += __shfl_xor_sync(0xffffffffu, s0, 2);
    s1 += __shfl_xor_sync(0xffffffffu, s1, 1);
    s1 += __shfl_xor_sync(0xffffffffu, s1, 2);
    if (tid4 == 0) {
        if (r0 < nkey) sb[r0] = s0;
        if (r1 < nkey) sb[r1] = s1;
    }

    #pragma unroll
    for (int jn = 0; jn < 8; jn++) {
        out_s[(8*jn+2*tid4  )*68 + 16*w5 + gp    ] = oc[jn][0];
        out_s[(8*jn+2*tid4+1)*68 + 16*w5 + gp    ] = oc[jn][1];
        out_s[(8*jn+2*tid4  )*68 + 16*w5 + gp + 8] = oc[jn][2];
        out_s[(8*jn+2*tid4+1)*68 + 16*w5 + gp + 8] = oc[jn][3];
    }
    __syncthreads();
    {
        int tq = t & 63, half = t >> 6;
        int q = tilebase + tq;
        if (q < nkey) {
            #pragma unroll 4
            for (int i = 0; i < 32; i++) {
                int c = half*32 + i;
                ob[(size_t)c*cs + q] = __float2half(out_s[c*68 + tq]);
            }
        }
    }
}

// ================= K3: merged row+col attention =================
__global__ __launch_bounds__(128, 6) void attn_kernel(
    const float* __restrict__ dwh, const float* __restrict__ dww)
{
    __shared__ float q_s[8*72];
    __shared__ float k_s[2][8*72];
    __shared__ __align__(16) __nv_bfloat16 v_s[2][64*72];
    __shared__ float dwt[Wn];
    float* out_s = (float*)v_s;   // alias: out staging reuses v buffers (dead after loop)

    int id = blockIdx.x;
    if (id < ROWBLKS) {
        int b = id / (8*Hn); int r = id % (8*Hn); int h = r >> 3; int wt = r & 7;
        attn_impl<false>(
            g_q + (size_t)b*CQn*HWn + h*Wn,
            g_k + (size_t)b*CQn*HWn + h*Wn,
            g_v + (size_t)b*Cn*HWn + h*Wn,
            g_ow + (size_t)b*Cn*HWn + h*Wn,
            g_sw + (size_t)(b*Hn + h)*Wn,
            (long)HWn, Wn, 8, wt*64, dww,
            q_s, k_s[0], k_s[1], v_s[0], v_s[1], dwt, out_s);
    } else {
        int j = id - ROWBLKS;
        int b = j / (5*Wn); int r = j % (5*Wn); int w = r / 5; int ht = r % 5;
        attn_impl<true>(
            g_qT + (size_t)(b*Wn + w)*CQn*Hp,
            g_kT + (size_t)(b*Wn + w)*CQn*Hp,
            g_vT + (size_t)(b*Wn + w)*Cn*Hp,
            g_ohT + (size_t)(b*Wn + w)*Cn*Hp,
            g_sh + (size_t)(b*Wn + w)*Hn,
            (long)Hp, Hn, 5, ht*64, dwh,
            q_s, k_s[0], k_s[1], v_s[0], v_s[1], dwt, out_s);
    }
}

// ================= K4: per-pixel 1/(s_h+s_w) =================
__global__ __launch_bounds__(256) void stats_kernel()
{
    int i = blockIdx.x*256 + threadIdx.x;
    if (i >= NPIX) return;
    int b = i / HWn, r = i - b*HWn;
    int h = r / Wn, w = r - h*Wn;
    float s = g_sw[i] + g_sh[(b*Wn + w)*Hn + h];
    g_inv[i] = 1.0f / s;
}

// ================= K5: combine + residual =================
__global__ __launch_bounds__(256) void combine_kernel(
    const float* __restrict__ x, const float* __restrict__ gamma_p,
    float* __restrict__ out)
{
    __shared__ __half tile[32][34];
    int bc = blockIdx.z;
    int b = bc >> 6, c = bc & 63;
    int w0 = blockIdx.x * 32, h0 = blockIdx.y * 32;
    int tx = threadIdx.x & 31, ty = threadIdx.x >> 5;

    #pragma unroll
    for (int k2 = 0; k2 < 4; k2++) {
        int w = w0 + ty + 8*k2, h = h0 + tx;
        __half v = __float2half(0.f);
        if (h < Hn) v = g_ohT[((size_t)(b*Wn+w)*Cn + c)*Hp + h];
        tile[ty+8*k2][tx] = v;
    }
    __syncthreads();
    float gamma = gamma_p[0];
    #pragma unroll
    for (int k2 = 0; k2 < 4; k2++) {
        int h = h0 + ty + 8*k2, w = w0 + tx;
        if (h >= Hn) continue;
        float oh = __half2float(tile[tx][ty+8*k2]);
        size_t idx = (size_t)(b*Cn + c)*HWn + h*Wn + w;
        float ow = __half2float(g_ow[idx]);
        float iv = g_inv[(b*Hn + h)*Wn + w];
        out[idx] = gamma * (oh + ow) * iv + x[idx];
    }
}

// ================= launch =================
extern "C" void kernel_launch(void* const* d_in, const int* in_sizes, int n_in,
                              void* d_out, int out_size)
{
    const float* x     = (const float*)d_in[0];
    const float* Wq    = (const float*)d_in[1];
    const float* bq    = (const float*)d_in[2];
    const float* Wk    = (const float*)d_in[3];
    const float* bk    = (const float*)d_in[4];
    const float* Wv    = (const float*)d_in[5];
    const float* bv    = (const float*)d_in[6];
    const float* gamma = (const float*)d_in[7];
    const float* dwh   = (const float*)d_in[8];
    const float* dww   = (const float*)d_in[9];
    float* out = (float*)d_out;

    proj_mma<<<NPIX/64, 128>>>(x, Wq, bq, Wk, bk, Wv, bv);

    transpose_all_kernel<<<dim3(Wn/32, (Hn+31)/32, Bn*80), 256>>>();

    attn_kernel<<<ROWBLKS + COLBLKS, 128>>>(dwh, dww);

    stats_kernel<<<(NPIX + 255)/256, 256>>>();

    combine_kernel<<<dim3(Wn/32, (Hn+31)/32, Bn*Cn), 256>>>(x, gamma, out);
}